// round 3
// baseline (speedup 1.0000x reference)
#include <cuda_runtime.h>
#include <cuda_fp16.h>

// V2STransformer: volume-to-slice affine resample with trilinear interpolation.
// vol: [B,H,W,D] f32 (B=8,H=160,W=160,D=96), trf: [B,S,12] (S=64), out: [B,H,W,S].
//
// Pass 1: transpose + pack: pair[b][h][d][w] = half2( v[w], v[min(w+1,W-1)] ).
//         One aligned 4B load then yields BOTH y-neighbors of a corner.
// Pass 2: lanes = w (warp shares the per-s affine); 4 half2 gather LDGs per
//         sample (was 8 f32) -> L1 wavefronts at the geometric floor.

#define BB 8
#define HH 160
#define WW 160
#define DD 96
#define SS 64
#define ST_RATIO 1.5f

// Packed pair volume: [b][h][d][w], half2 = (v[w], v[w+1 clamped]). 78.6 MB.
__device__ __half2 vol_p_buf[(size_t)BB * HH * DD * WW];

// ---------------------------------------------------------------------------
// Pass 1: per-(b,h) transpose [W, D] -> [D, W] with y-pair packing to half2.
// ---------------------------------------------------------------------------
__global__ __launch_bounds__(256)
void v2s_pack_kernel(const float* __restrict__ vol) {
    __shared__ float tile[33][33];           // [w_local][d_local], pad to 33

    const int bh = blockIdx.z;               // b*H + h
    const int d0 = blockIdx.x * 32;
    const int w0 = blockIdx.y * 32;
    const int tx = threadIdx.x;              // 32 (d lane on load, w lane on store)
    const int ty = threadIdx.y;              // 8

    const float* __restrict__ src = vol + (size_t)bh * WW * DD;     // [w][d]
    __half2* __restrict__ dst = vol_p_buf + (size_t)bh * DD * WW;   // [d][w]

    // Load 33 w-rows (need w0+32 for the pair), coalesced along d.
    #pragma unroll
    for (int i = ty; i < 33; i += 8) {
        const int w = min(w0 + i, WW - 1);   // clamp only matters for last tile
        tile[i][tx] = src[(size_t)w * DD + (d0 + tx)];
    }
    __syncthreads();

    // Store: lanes along w, rows along d. pair = (v[w], v[w+1]).
    #pragma unroll
    for (int i = ty; i < 32; i += 8) {
        const float a = tile[tx][i];
        const float c = tile[tx + 1][i];
        dst[(size_t)(d0 + i) * WW + (w0 + tx)] = __floats2half2_rn(a, c);
    }
}

// ---------------------------------------------------------------------------
// Pass 2: main resample. Block = (32 w-lanes, 8), covers (1 h, 32 w, 64 s).
// ---------------------------------------------------------------------------
__global__ __launch_bounds__(256, 4)
void v2s_main_kernel(const float* __restrict__ trf,
                     float* __restrict__ out) {
    __shared__ float As[SS][13];             // identity pre-added, pad 13
    __shared__ float tile[32][SS + 1];       // [w_local][s]

    const int b  = blockIdx.z;
    const int h  = blockIdx.y;
    const int w0 = blockIdx.x * 32;
    const int tx = threadIdx.x;              // w lane: 0..31
    const int ty = threadIdx.y;              // 0..7
    const int tid = ty * 32 + tx;

    // Load this batch's 64 affines (768 floats), add identity.
    #pragma unroll
    for (int k = tid; k < SS * 12; k += 256) {
        const int ss = k / 12;
        const int e  = k % 12;
        float v = trf[((size_t)b * SS + ss) * 12 + e];
        if (e == 0 || e == 5 || e == 10) v += 1.0f;
        As[ss][e] = v;
    }
    __syncthreads();

    const __half2* __restrict__ vp = vol_p_buf + (size_t)b * (HH * DD * WW);
    const float fi = (float)h;
    const float fj = (float)(w0 + tx);

    #pragma unroll
    for (int k = 0; k < 8; k++) {
        const int s = ty * 8 + k;            // all lanes in warp share s
        const float fz = (float)s * ST_RATIO;
        const float* A = As[s];

        float x = fmaf(A[0], fi, fmaf(A[1], fj, fmaf(A[2],  fz, A[3])));
        float y = fmaf(A[4], fi, fmaf(A[5], fj, fmaf(A[6],  fz, A[7])));
        float z = fmaf(A[8], fi, fmaf(A[9], fj, fmaf(A[10], fz, A[11])));

        x = fminf(fmaxf(x, 0.0f), (float)(HH - 1));
        y = fminf(fmaxf(y, 0.0f), (float)(WW - 1));
        z = fminf(fmaxf(z, 0.0f), (float)(DD - 1));

        const int x0 = __float2int_rd(x);
        const int y0 = __float2int_rd(y);
        const int z0 = __float2int_rd(z);
        const float dx = x - (float)x0;
        const float dy = y - (float)y0;
        const float dz = z - (float)z0;

        // pair layout: idx = (x*D + z)*W + y ; pair gives (v[y], v[y+1])
        const int base = (x0 * DD + z0) * WW + y0;
        const int zoff = (z0 < DD - 1) ? WW : 0;
        const int xoff = (x0 < HH - 1) ? DD * WW : 0;

        const float2 p00 = __half22float2(__ldg(vp + base));
        const float2 p01 = __half22float2(__ldg(vp + base + zoff));
        const float2 p10 = __half22float2(__ldg(vp + base + xoff));
        const float2 p11 = __half22float2(__ldg(vp + base + xoff + zoff));

        // y-lerp from pairs, then z, then x
        const float c00 = fmaf(dy, p00.y - p00.x, p00.x);   // (x0,z0)
        const float c01 = fmaf(dy, p01.y - p01.x, p01.x);   // (x0,z1)
        const float c10 = fmaf(dy, p10.y - p10.x, p10.x);   // (x1,z0)
        const float c11 = fmaf(dy, p11.y - p11.x, p11.x);   // (x1,z1)
        const float c0  = fmaf(dz, c01 - c00, c00);
        const float c1  = fmaf(dz, c11 - c10, c10);
        const float r   = fmaf(dx, c1 - c0, c0);

        tile[tx][s] = r;
    }
    __syncthreads();

    // Coalesced write: consecutive tids -> consecutive s.
    float* __restrict__ ob = out + (((size_t)b * HH + h) * WW + w0) * SS;
    #pragma unroll
    for (int idx = tid; idx < 32 * SS; idx += 256) {
        const int wl = idx >> 6;
        const int s  = idx & 63;
        ob[(size_t)wl * SS + s] = tile[wl][s];
    }
}

extern "C" void kernel_launch(void* const* d_in, const int* in_sizes, int n_in,
                              void* d_out, int out_size) {
    const float* vol = (const float*)d_in[0];
    const float* trf = (const float*)d_in[1];
    float* out = (float*)d_out;

    {
        dim3 block(32, 8, 1);
        dim3 grid(DD / 32, WW / 32, BB * HH);   // (3, 5, 1280)
        v2s_pack_kernel<<<grid, block>>>(vol);
    }
    {
        dim3 block(32, 8, 1);
        dim3 grid(WW / 32, HH, BB);             // (5, 160, 8)
        v2s_main_kernel<<<grid, block>>>(trf, out);
    }
}

// round 4
// speedup vs baseline: 1.1698x; 1.1698x over previous
#include <cuda_runtime.h>
#include <cuda_fp16.h>

// V2STransformer: volume-to-slice affine resample with trilinear interpolation.
// vol: [B,H,W,D] f32 (B=8,H=160,W=160,D=96), trf: [B,S,12] (S=64), out: [B,H,W,S].
//
// Pass 1: transpose+pack: pair[b][h][d][w] = half2( v[w], v[min(w+1,W-1)] ).
//         One block per 80-row half plane, padded smem, conflict-free.
// Pass 2: lanes = w; per-block precomputed affine partials; 4 half2 gathers
//         per sample (y-pair comes packaged in each load).

#define BB 8
#define HH 160
#define WW 160
#define DD 96
#define SS 64
#define ST_RATIO 1.5f
#define WCHUNK 80

// Packed pair volume: [b][h][d][w], half2 = (v[w], v[w+1 clamped]). 78.6 MB.
__device__ __half2 vol_p_buf[(size_t)BB * HH * DD * WW];

// ---------------------------------------------------------------------------
// Pass 1: per-(b,h) half-plane transpose [Wchunk, D] -> [D, Wchunk] + pairing.
// ---------------------------------------------------------------------------
__global__ __launch_bounds__(256)
void v2s_pack_kernel(const float* __restrict__ vol) {
    __shared__ float tile[(WCHUNK + 1) * 97];   // [w_local][d], row stride 97

    const int w0 = blockIdx.x * WCHUNK;         // 0 or 80
    const int bh = blockIdx.y;                  // b*H + h
    const int tid = threadIdx.x;

    const float* __restrict__ src = vol + (size_t)bh * WW * DD;     // [w][d]
    __half2* __restrict__ dst = vol_p_buf + (size_t)bh * DD * WW;   // [d][w]

    // Load (WCHUNK+1) w-rows x 96 d, coalesced along d; conflict-free STS.
    #pragma unroll 4
    for (int idx = tid; idx < (WCHUNK + 1) * DD; idx += 256) {
        const int wl = idx / DD;
        const int d  = idx - wl * DD;
        const int w  = min(w0 + wl, WW - 1);    // clamp for the boundary row
        tile[wl * 97 + d] = src[(size_t)w * DD + d];
    }
    __syncthreads();

    // Emit pairs: lanes along w (stride-97 smem reads, conflict-free),
    // coalesced 4B stores along w.
    #pragma unroll 4
    for (int idx = tid; idx < DD * WCHUNK; idx += 256) {
        const int d  = idx / WCHUNK;
        const int wl = idx - d * WCHUNK;
        const float a = tile[wl * 97 + d];
        const float c = tile[(wl + 1) * 97 + d];
        dst[(size_t)d * WW + (w0 + wl)] = __floats2half2_rn(a, c);
    }
}

// ---------------------------------------------------------------------------
// Pass 2: main resample. Block = (32 w-lanes, 8), covers (1 h, 32 w, 64 s).
// ---------------------------------------------------------------------------
__global__ __launch_bounds__(256, 4)
void v2s_main_kernel(const float* __restrict__ trf,
                     float* __restrict__ out) {
    // Per-s fused affine partials: for axis r, coord = fmaf(coef, fj, P)
    // where P = a_i*fi + a_z*fz + a_3 folds in h and z = s*ST_RATIO.
    __shared__ float Pre[SS][8];             // [s][{cx,Px,cy,Py,cz,Pz,_,_}]
    __shared__ float tile[32][SS + 1];       // [w_local][s]

    const int b  = blockIdx.z;
    const int h  = blockIdx.y;
    const int w0 = blockIdx.x * 32;
    const int tx = threadIdx.x;              // w lane: 0..31
    const int ty = threadIdx.y;              // 0..7
    const int tid = ty * 32 + tx;

    const float fi = (float)h;

    // 64 s * 3 axes = 192 precompute items.
    for (int it = tid; it < SS * 3; it += 256) {
        const int s = it / 3;
        const int r = it - s * 3;
        const float* t = trf + ((size_t)b * SS + s) * 12 + r * 4;
        const float a0 = t[0] + (r == 0 ? 1.0f : 0.0f);
        const float a1 = t[1] + (r == 1 ? 1.0f : 0.0f);
        const float a2 = t[2] + (r == 2 ? 1.0f : 0.0f);
        const float a3 = t[3];
        const float fz = (float)s * ST_RATIO;
        Pre[s][r * 2]     = a1;
        Pre[s][r * 2 + 1] = fmaf(a0, fi, fmaf(a2, fz, a3));
    }
    __syncthreads();

    const __half2* __restrict__ vp = vol_p_buf + (size_t)b * (HH * DD * WW);
    const float fj = (float)(w0 + tx);

    #pragma unroll
    for (int k = 0; k < 8; k++) {
        const int s = ty * 8 + k;            // all lanes in warp share s
        const float* P = Pre[s];

        float x = fmaf(P[0], fj, P[1]);
        float y = fmaf(P[2], fj, P[3]);
        float z = fmaf(P[4], fj, P[5]);

        x = fminf(fmaxf(x, 0.0f), (float)(HH - 1));
        y = fminf(fmaxf(y, 0.0f), (float)(WW - 1));
        z = fminf(fmaxf(z, 0.0f), (float)(DD - 1));

        const int x0 = __float2int_rd(x);
        const int y0 = __float2int_rd(y);
        const int z0 = __float2int_rd(z);
        const float dx = x - (float)x0;
        const float dy = y - (float)y0;
        const float dz = z - (float)z0;

        // pair layout: idx = (x*D + z)*W + y ; pair = (v[y], v[y+1])
        const int base = (x0 * DD + z0) * WW + y0;
        const int zoff = (z0 < DD - 1) ? WW : 0;
        const int xoff = (x0 < HH - 1) ? DD * WW : 0;

        const float2 p00 = __half22float2(__ldg(vp + base));
        const float2 p01 = __half22float2(__ldg(vp + base + zoff));
        const float2 p10 = __half22float2(__ldg(vp + base + xoff));
        const float2 p11 = __half22float2(__ldg(vp + base + xoff + zoff));

        // y-lerp from pairs, then z, then x
        const float c00 = fmaf(dy, p00.y - p00.x, p00.x);
        const float c01 = fmaf(dy, p01.y - p01.x, p01.x);
        const float c10 = fmaf(dy, p10.y - p10.x, p10.x);
        const float c11 = fmaf(dy, p11.y - p11.x, p11.x);
        const float c0  = fmaf(dz, c01 - c00, c00);
        const float c1  = fmaf(dz, c11 - c10, c10);
        const float r   = fmaf(dx, c1 - c0, c0);

        tile[tx][s] = r;
    }
    __syncthreads();

    // Coalesced write: consecutive tids -> consecutive s.
    float* __restrict__ ob = out + (((size_t)b * HH + h) * WW + w0) * SS;
    #pragma unroll
    for (int idx = tid; idx < 32 * SS; idx += 256) {
        const int wl = idx >> 6;
        const int s  = idx & 63;
        ob[(size_t)wl * SS + s] = tile[wl][s];
    }
}

extern "C" void kernel_launch(void* const* d_in, const int* in_sizes, int n_in,
                              void* d_out, int out_size) {
    const float* vol = (const float*)d_in[0];
    const float* trf = (const float*)d_in[1];
    float* out = (float*)d_out;

    {
        dim3 block(256, 1, 1);
        dim3 grid(WW / WCHUNK, BB * HH, 1);     // (2, 1280)
        v2s_pack_kernel<<<grid, block>>>(vol);
    }
    {
        dim3 block(32, 8, 1);
        dim3 grid(WW / 32, HH, BB);             // (5, 160, 8)
        v2s_main_kernel<<<grid, block>>>(trf, out);
    }
}